// round 11
// baseline (speedup 1.0000x reference)
#include <cuda_runtime.h>
#include <cuda_fp16.h>

#define HID 64
#define SEQT 512
#define BROWS 32
#define LDH 72            // padded halves per h row (conflict-free ldmatrix)
#define NTHREADS 1024     // 32 warps: 16 x layer0 (M-split), 16 x layer1
#define NL0 512           // threads in L0 group
#define XCH 128           // x chunk length staged in smem
#define XLD 33            // padded float stride for xs rows
#define HSTRIDE (BROWS * LDH)   // halves per h buffer

// named barriers: 1..3 = free[slot], 4..6 = full[slot], 7 = L0 group
#define BAR_FREE 1
#define BAR_FULL 4
#define BAR_L0G  7

#define BSYNC(id, cnt)   asm volatile("bar.sync %0, %1;"   :: "r"(id), "r"(cnt) : "memory")
#define BARRIVE(id, cnt) asm volatile("bar.arrive %0, %1;" :: "r"(id), "r"(cnt) : "memory")
#define MEMBAR_CTA()     asm volatile("membar.cta;" ::: "memory")

__device__ __forceinline__ unsigned smem_u32(const void* p) {
    return (unsigned)__cvta_generic_to_shared(p);
}

__device__ __forceinline__ void ldsm4(unsigned a[4], unsigned addr) {
    asm volatile("ldmatrix.sync.aligned.m8n8.x4.shared.b16 {%0,%1,%2,%3}, [%4];\n"
        : "=r"(a[0]), "=r"(a[1]), "=r"(a[2]), "=r"(a[3]) : "r"(addr));
}

__device__ __forceinline__ void mma16816(float c[4], const unsigned a[4], const unsigned b[2]) {
    asm volatile("mma.sync.aligned.m16n8k16.row.col.f32.f16.f16.f32 "
        "{%0,%1,%2,%3},{%4,%5,%6,%7},{%8,%9},{%0,%1,%2,%3};\n"
        : "+f"(c[0]), "+f"(c[1]), "+f"(c[2]), "+f"(c[3])
        : "r"(a[0]), "r"(a[1]), "r"(a[2]), "r"(a[3]), "r"(b[0]), "r"(b[1]));
}

__device__ __forceinline__ float tanh_hw(float x) {
    float y;
    asm("tanh.approx.f32 %0, %1;" : "=f"(y) : "f"(x));
    return y;
}

// LSTM cell, i/f/o pre-activations PRE-SCALED by 0.5 (folded into weights/bias).
// sigmoid(2x') = 0.5*tanh(x')+0.5. 5 MUFU + 6 fma-pipe ops.
__device__ __forceinline__ float2 celltanh_ps(float ip, float fp, float gp, float op, float c) {
    float ti = tanh_hw(ip);
    float tf = tanh_hw(fp);
    float to = tanh_hw(op);
    float tg = tanh_hw(gp);
    float si = fmaf(ti, 0.5f, 0.5f);
    float sf = fmaf(tf, 0.5f, 0.5f);
    float so = fmaf(to, 0.5f, 0.5f);
    float cn = fmaf(sf, c, si * tg);
    float tc = tanh_hw(cn);
    return make_float2(cn, so * tc);
}

__global__ void __launch_bounds__(NTHREADS, 1)
lstm2_kernel(const float* __restrict__ x,
             const float* __restrict__ w_ih0, const float* __restrict__ w_hh0,
             const float* __restrict__ b_ih0, const float* __restrict__ b_hh0,
             const float* __restrict__ w_ih1, const float* __restrict__ w_hh1,
             const float* __restrict__ b_ih1, const float* __restrict__ b_hh1,
             const float* __restrict__ w_lin, const float* __restrict__ b_lin,
             float* __restrict__ out)
{
    __shared__ __half hbuf[5][HSTRIDE];  // [0..2]=h1 ring, [3,4]=h2 double buffer
    __shared__ float2 bias0p[128];   // layer0 bias, 8-colgroup permuted (i/f/o x0.5)
    __shared__ float2 wih0p[128];    // layer0 input weights, same layout
    __shared__ float2 bias1p[128];   // layer1 bias, 16-warp permuted (i/f/o x0.5)
    __shared__ float  wlin_s[HID];
    __shared__ float  xs[XCH * XLD]; // staged x chunk, transposed [k][row]

    const int tid  = threadIdx.x;
    const int wid  = tid >> 5;
    const int lane = tid & 31;
    const int r0   = blockIdx.x * BROWS;

    // ---------------- init: permuted bias / w_ih0 tables ----------------
    if (tid < 256) {
        {   // layer0: 8 col-groups x 32 cols: idx = cg*32 + j*8 + c
            int cg = tid >> 5, rem = tid & 31, j = rem >> 3, c = rem & 7;
            int u = cg * 8 + (j >> 1) * 4 + (c >> 1);
            int g = (j & 1) * 2 + (c & 1);
            int row = g * HID + u;
            float sc = (g == 2) ? 1.0f : 0.5f;
            ((float*)bias0p)[tid] = (b_ih0[row] + b_hh0[row]) * sc;
            ((float*)wih0p)[tid]  = w_ih0[row] * sc;
        }
        {   // layer1: 16 warps x 16 cols: idx = w1*16 + j*8 + c
            int w1 = tid >> 4, rem = tid & 15, j = rem >> 3, c = rem & 7;
            int u = w1 * 4 + (c >> 1);
            int g = j * 2 + (c & 1);
            int row = g * HID + u;
            float sc = (g == 2) ? 1.0f : 0.5f;
            ((float*)bias1p)[tid] = (b_ih1[row] + b_hh1[row]) * sc;
        }
    }
    if (tid < HID) wlin_s[tid] = w_lin[tid];
    for (int i = tid; i < HSTRIDE; i += NTHREADS) {
        hbuf[2][i] = __float2half(0.0f);   // h1[-1]
        hbuf[3][i] = __float2half(0.0f);
        hbuf[4][i] = __float2half(0.0f);   // h2[-1]
    }

    // ---------------- preload weight B-fragments into registers ----------------
    unsigned wf[32];
    float    cs[4];
    #pragma unroll
    for (int i = 0; i < 4; i++) cs[i] = 0.0f;

    const int cB = lane >> 2;
    const int kq = lane & 3;

    if (wid < 16) {
        // L0 warp: col-group cg (32 gate-cols), row-tile rt (16 rows)
        const int cg = wid & 7;
        #pragma unroll
        for (int j = 0; j < 4; j++) {
            int u = cg * 8 + (j >> 1) * 4 + (cB >> 1);
            int g = (j & 1) * 2 + (cB & 1);
            float sc = (g == 2) ? 1.0f : 0.5f;
            const float* wr = w_hh0 + (g * HID + u) * HID;
            #pragma unroll
            for (int kt = 0; kt < 4; kt++) {
                int k0 = kt * 16 + 2 * kq;
                __half2 lo = __floats2half2_rn(wr[k0] * sc,     wr[k0 + 1] * sc);
                __half2 hi = __floats2half2_rn(wr[k0 + 8] * sc, wr[k0 + 9] * sc);
                wf[(j * 4 + kt) * 2 + 0] = *(unsigned*)&lo;
                wf[(j * 4 + kt) * 2 + 1] = *(unsigned*)&hi;
            }
        }
    } else {
        const int w1 = wid - 16;
        #pragma unroll
        for (int m = 0; m < 2; m++) {
            const float* W = m ? w_hh1 : w_ih1;
            #pragma unroll
            for (int j = 0; j < 2; j++) {
                int u = w1 * 4 + (cB >> 1);
                int g = j * 2 + (cB & 1);
                float sc = (g == 2) ? 1.0f : 0.5f;
                const float* wr = W + (g * HID + u) * HID;
                #pragma unroll
                for (int kt = 0; kt < 4; kt++) {
                    int k0 = kt * 16 + 2 * kq;
                    __half2 lo = __floats2half2_rn(wr[k0] * sc,     wr[k0 + 1] * sc);
                    __half2 hi = __floats2half2_rn(wr[k0 + 8] * sc, wr[k0 + 9] * sc);
                    wf[((m * 2 + j) * 4 + kt) * 2 + 0] = *(unsigned*)&lo;
                    wf[((m * 2 + j) * 4 + kt) * 2 + 1] = *(unsigned*)&hi;
                }
            }
        }
    }
    __syncthreads();

    const unsigned hbase   = smem_u32(hbuf[0]);
    const unsigned hbytes  = HSTRIDE * 2;                       // bytes per h buffer
    const unsigned laneoff = 2u * ((lane & 15) * LDH + (lane >> 4) * 8);

    if (wid < 16) {
        // ===== L0 producer group (512 threads), M-split: 16 rows x 32 cols/warp =====
        const int cg = wid & 7;
        const int rt = wid >> 3;            // row tile: rows rt*16 .. rt*16+15
        const unsigned rowoff = rt * (16 * LDH * 2);
        float2 b_if[2], b_go[2], w_if[2], w_go[2];
        #pragma unroll
        for (int p = 0; p < 2; p++) {
            b_if[p] = bias0p[cg * 16 + (2 * p) * 4 + (lane & 3)];
            b_go[p] = bias0p[cg * 16 + (2 * p + 1) * 4 + (lane & 3)];
            w_if[p] = wih0p[cg * 16 + (2 * p) * 4 + (lane & 3)];
            w_go[p] = wih0p[cg * 16 + (2 * p + 1) * 4 + (lane & 3)];
        }
        int s = 0, sp = 2;
        for (int k = 0; k < SEQT; ++k) {
            if ((k & (XCH - 1)) == 0) {
                if (k) BSYNC(BAR_L0G, NL0);          // peers done with old chunk
                for (int i = tid; i < BROWS * XCH; i += NL0) {
                    int row = i >> 7, kl = i & (XCH - 1);
                    xs[kl * XLD + row] = x[(r0 + row) * SEQT + k + kl];
                }
                BSYNC(BAR_L0G, NL0);
            }
            if (k >= 3)      BSYNC(BAR_FREE + s, NTHREADS);  // L1 consumed slot s; groups L0
            else if (k >= 1) BSYNC(BAR_L0G, NL0);            // order peers' h1[k-1] writes

            const int kk = (k & (XCH - 1)) * XLD;
            float xv[2];
            xv[0] = xs[kk + rt * 16 + (lane >> 2)];
            xv[1] = xs[kk + rt * 16 + (lane >> 2) + 8];

            const unsigned h1rd = hbase + sp * hbytes + rowoff + laneoff;
            float cf[16];
            #pragma unroll
            for (int p = 0; p < 2; p++) {
                cf[(2*p)*4+0] = b_if[p].x; cf[(2*p)*4+1] = b_if[p].y;
                cf[(2*p)*4+2] = b_if[p].x; cf[(2*p)*4+3] = b_if[p].y;
                cf[(2*p+1)*4+0] = b_go[p].x; cf[(2*p+1)*4+1] = b_go[p].y;
                cf[(2*p+1)*4+2] = b_go[p].x; cf[(2*p+1)*4+3] = b_go[p].y;
            }
            #pragma unroll
            for (int kt = 0; kt < 4; kt++) {
                unsigned am[4];
                ldsm4(am, h1rd + kt * 32);
                #pragma unroll
                for (int j = 0; j < 4; j++)
                    mma16816(&cf[j * 4], am, &wf[(j * 4 + kt) * 2]);
            }
            #pragma unroll
            for (int p = 0; p < 2; p++) {
                #pragma unroll
                for (int rh = 0; rh < 2; rh++) {
                    float xr = xv[rh];
                    float ip = fmaf(xr, w_if[p].x, cf[(2*p)*4 + rh*2 + 0]);
                    float fp = fmaf(xr, w_if[p].y, cf[(2*p)*4 + rh*2 + 1]);
                    float gp = fmaf(xr, w_go[p].x, cf[(2*p+1)*4 + rh*2 + 0]);
                    float op = fmaf(xr, w_go[p].y, cf[(2*p+1)*4 + rh*2 + 1]);
                    int ci = p * 2 + rh;
                    float2 ch = celltanh_ps(ip, fp, gp, op, cs[ci]);
                    cs[ci] = ch.x;
                    int r = rt * 16 + (lane >> 2) + 8 * rh;
                    int u = cg * 8 + 4 * p + (lane & 3);
                    hbuf[s][r * LDH + u] = __float2half_rn(ch.y);
                }
            }
            MEMBAR_CTA();                       // publish h1[s] stores
            BARRIVE(BAR_FULL + s, NTHREADS);
            sp = s; s = (s == 2) ? 0 : s + 1;
        }
    } else {
        // =========== L1 consumer group (512 threads) — R5 protocol ===========
        const int w1 = wid - 16;
        const float2 bif = bias1p[w1 * 8 + (lane & 3)];
        const float2 bgo = bias1p[w1 * 8 + 4 + (lane & 3)];
        const int u1 = w1 * 4 + (lane & 3);
        int s = 0;
        for (int k = 0; k < SEQT; ++k) {
            BSYNC(BAR_FULL + s, NTHREADS);      // h1[k] ready; also groups L1 (fences h2)
            const unsigned h1rd = hbase + s * hbytes + laneoff;
            const unsigned h2rd = hbase + (3 + ((k + 1) & 1)) * hbytes + laneoff;
            #pragma unroll
            for (int mt = 0; mt < 2; mt++) {
                float cf[8];
                cf[0] = bif.x; cf[1] = bif.y; cf[2] = bif.x; cf[3] = bif.y;
                cf[4] = bgo.x; cf[5] = bgo.y; cf[6] = bgo.x; cf[7] = bgo.y;
                #pragma unroll
                for (int kt = 0; kt < 4; kt++) {       // h1_k @ w_ih1^T
                    unsigned am[4];
                    ldsm4(am, h1rd + mt * (16 * LDH * 2) + kt * 32);
                    mma16816(&cf[0], am, &wf[kt * 2]);
                    mma16816(&cf[4], am, &wf[(4 + kt) * 2]);
                }
                #pragma unroll
                for (int kt = 0; kt < 4; kt++) {       // h2_{k-1} @ w_hh1^T
                    unsigned am[4];
                    ldsm4(am, h2rd + mt * (16 * LDH * 2) + kt * 32);
                    mma16816(&cf[0], am, &wf[(8 + kt) * 2]);
                    mma16816(&cf[4], am, &wf[(12 + kt) * 2]);
                }
                #pragma unroll
                for (int rh = 0; rh < 2; rh++) {
                    float ip = cf[rh * 2 + 0];
                    float fp = cf[rh * 2 + 1];
                    float gp = cf[4 + rh * 2 + 0];
                    float op = cf[4 + rh * 2 + 1];
                    int ci = mt * 2 + rh;
                    float2 ch = celltanh_ps(ip, fp, gp, op, cs[ci]);
                    cs[ci] = ch.x;
                    int r = 16 * mt + (lane >> 2) + 8 * rh;
                    hbuf[3 + (k & 1)][r * LDH + u1] = __float2half_rn(ch.y);
                }
            }
            BARRIVE(BAR_FREE + s, NTHREADS);    // h1[s] consumed
            s = (s == 2) ? 0 : s + 1;
        }
    }
    __syncthreads();

    // ---------------- linear head on h2_{T-1} ----------------
    if (tid < BROWS) {
        const __half* h2f = hbuf[3 + ((SEQT - 1) & 1)];
        float acc = b_lin[0];
        #pragma unroll
        for (int u = 0; u < HID; u++)
            acc += __half2float(h2f[tid * LDH + u]) * wlin_s[u];
        out[r0 + tid] = acc;
    }
}

extern "C" void kernel_launch(void* const* d_in, const int* in_sizes, int n_in,
                              void* d_out, int out_size) {
    const float* x     = (const float*)d_in[0];
    const float* w_ih0 = (const float*)d_in[1];
    const float* w_hh0 = (const float*)d_in[2];
    const float* b_ih0 = (const float*)d_in[3];
    const float* b_hh0 = (const float*)d_in[4];
    const float* w_ih1 = (const float*)d_in[5];
    const float* w_hh1 = (const float*)d_in[6];
    const float* b_ih1 = (const float*)d_in[7];
    const float* b_hh1 = (const float*)d_in[8];
    const float* w_lin = (const float*)d_in[9];
    const float* b_lin = (const float*)d_in[10];

    const int B = in_sizes[0] / SEQT;   // 4096
    const int grid = B / BROWS;         // 128

    lstm2_kernel<<<grid, NTHREADS>>>(x, w_ih0, w_hh0, b_ih0, b_hh0,
                                     w_ih1, w_hh1, b_ih1, b_hh1,
                                     w_lin, b_lin, (float*)d_out);
}

// round 13
// speedup vs baseline: 1.1073x; 1.1073x over previous
#include <cuda_runtime.h>
#include <cuda_fp16.h>

#define HID 64
#define SEQT 512
#define BROWS 32
#define LDH 72            // padded halves per h row (conflict-free ldmatrix)
#define NTHREADS 1024     // 32 warps: 16 x layer0, 16 x layer1
#define NL0 512           // threads in L0 group
#define XCH 128           // x chunk length staged in smem
#define XLD 33            // padded float stride for xs rows
#define HSTRIDE (BROWS * LDH)   // halves per h buffer
#define RB (16 * LDH * 2)       // bytes per 16-row block of an h buffer

// named barriers: 1..3 = free[slot], 4..6 = full[slot], 7 = L0 group
#define BAR_FREE 1
#define BAR_FULL 4
#define BAR_L0G  7

#define BSYNC(id, cnt)   asm volatile("bar.sync %0, %1;"   :: "r"(id), "r"(cnt) : "memory")
#define BARRIVE(id, cnt) asm volatile("bar.arrive %0, %1;" :: "r"(id), "r"(cnt) : "memory")
#define MEMBAR_CTA()     asm volatile("membar.cta;" ::: "memory")

__device__ __forceinline__ unsigned smem_u32(const void* p) {
    return (unsigned)__cvta_generic_to_shared(p);
}

__device__ __forceinline__ void ldsm4(unsigned a[4], unsigned addr) {
    asm volatile("ldmatrix.sync.aligned.m8n8.x4.shared.b16 {%0,%1,%2,%3}, [%4];\n"
        : "=r"(a[0]), "=r"(a[1]), "=r"(a[2]), "=r"(a[3]) : "r"(addr));
}

__device__ __forceinline__ void mma16816(float c[4], const unsigned a[4], const unsigned b[2]) {
    asm volatile("mma.sync.aligned.m16n8k16.row.col.f32.f16.f16.f32 "
        "{%0,%1,%2,%3},{%4,%5,%6,%7},{%8,%9},{%0,%1,%2,%3};\n"
        : "+f"(c[0]), "+f"(c[1]), "+f"(c[2]), "+f"(c[3])
        : "r"(a[0]), "r"(a[1]), "r"(a[2]), "r"(a[3]), "r"(b[0]), "r"(b[1]));
}

__device__ __forceinline__ float tanh_hw(float x) {
    float y;
    asm("tanh.approx.f32 %0, %1;" : "=f"(y) : "f"(x));
    return y;
}

// LSTM cell, i/f/o pre-activations PRE-SCALED by 0.5 (folded into weights/bias).
// sigmoid(2x') = 0.5*tanh(x')+0.5. 5 MUFU + 6 fma-pipe ops.
__device__ __forceinline__ float2 celltanh_ps(float ip, float fp, float gp, float op, float c) {
    float ti = tanh_hw(ip);
    float tf = tanh_hw(fp);
    float to = tanh_hw(op);
    float tg = tanh_hw(gp);
    float si = fmaf(ti, 0.5f, 0.5f);
    float sf = fmaf(tf, 0.5f, 0.5f);
    float so = fmaf(to, 0.5f, 0.5f);
    float cn = fmaf(sf, c, si * tg);
    float tc = tanh_hw(cn);
    return make_float2(cn, so * tc);
}

__global__ void __launch_bounds__(NTHREADS, 1)
lstm2_kernel(const float* __restrict__ x,
             const float* __restrict__ w_ih0, const float* __restrict__ w_hh0,
             const float* __restrict__ b_ih0, const float* __restrict__ b_hh0,
             const float* __restrict__ w_ih1, const float* __restrict__ w_hh1,
             const float* __restrict__ b_ih1, const float* __restrict__ b_hh1,
             const float* __restrict__ w_lin, const float* __restrict__ b_lin,
             float* __restrict__ out)
{
    __shared__ __half hbuf[5][HSTRIDE];  // [0..2]=h1 ring, [3,4]=h2 double buffer
    __shared__ float2 bias0p[128];   // layer0 combined bias, permuted (i/f/o x0.5)
    __shared__ float2 wih0p[128];    // layer0 input weights, permuted (i/f/o x0.5)
    __shared__ float2 bias1p[128];   // layer1 combined bias, permuted (i/f/o x0.5)
    __shared__ float  wlin_s[HID];
    __shared__ float  xs[XCH * XLD]; // staged x chunk, transposed [k][row]

    const int tid  = threadIdx.x;
    const int wid  = tid >> 5;
    const int lane = tid & 31;
    const int r0   = blockIdx.x * BROWS;

    // ---------------- init: permuted bias / w_ih0 tables ----------------
    // Both layers: 16 warps x 16 gate-cols. idx = w*16 + j*8 + c,
    // unit u = w*4 + (c>>1), gate g = j*2 + (c&1). Gate 2 (=g) unscaled; i/f/o x0.5.
    if (tid < 256) {
        int w = tid >> 4, rem = tid & 15, j = rem >> 3, c = rem & 7;
        int u = w * 4 + (c >> 1);
        int g = j * 2 + (c & 1);
        int row = g * HID + u;
        float sc = (g == 2) ? 1.0f : 0.5f;
        ((float*)bias0p)[tid] = (b_ih0[row] + b_hh0[row]) * sc;
        ((float*)wih0p)[tid]  = w_ih0[row] * sc;
        ((float*)bias1p)[tid] = (b_ih1[row] + b_hh1[row]) * sc;
    }
    if (tid < HID) wlin_s[tid] = w_lin[tid];
    for (int i = tid; i < HSTRIDE; i += NTHREADS) {
        hbuf[2][i] = __float2half(0.0f);   // h1[-1]
        hbuf[3][i] = __float2half(0.0f);
        hbuf[4][i] = __float2half(0.0f);   // h2[-1]
    }

    // ---------------- preload weight B-fragments into registers ----------------
    unsigned wf[32];          // L0 uses [0..15], L1 uses all 32
    float    cs[4];
    #pragma unroll
    for (int i = 0; i < 4; i++) cs[i] = 0.0f;

    const int cB = lane >> 2;
    const int kq = lane & 3;

    if (wid < 16) {
        const int w = wid;
        #pragma unroll
        for (int j = 0; j < 2; j++) {
            int u = w * 4 + (cB >> 1);
            int g = j * 2 + (cB & 1);
            float sc = (g == 2) ? 1.0f : 0.5f;
            const float* wr = w_hh0 + (g * HID + u) * HID;
            #pragma unroll
            for (int kt = 0; kt < 4; kt++) {
                int k0 = kt * 16 + 2 * kq;
                __half2 lo = __floats2half2_rn(wr[k0] * sc,     wr[k0 + 1] * sc);
                __half2 hi = __floats2half2_rn(wr[k0 + 8] * sc, wr[k0 + 9] * sc);
                wf[(j * 4 + kt) * 2 + 0] = *(unsigned*)&lo;
                wf[(j * 4 + kt) * 2 + 1] = *(unsigned*)&hi;
            }
        }
    } else {
        const int w1 = wid - 16;
        #pragma unroll
        for (int m = 0; m < 2; m++) {
            const float* W = m ? w_hh1 : w_ih1;
            #pragma unroll
            for (int j = 0; j < 2; j++) {
                int u = w1 * 4 + (cB >> 1);
                int g = j * 2 + (cB & 1);
                float sc = (g == 2) ? 1.0f : 0.5f;
                const float* wr = W + (g * HID + u) * HID;
                #pragma unroll
                for (int kt = 0; kt < 4; kt++) {
                    int k0 = kt * 16 + 2 * kq;
                    __half2 lo = __floats2half2_rn(wr[k0] * sc,     wr[k0 + 1] * sc);
                    __half2 hi = __floats2half2_rn(wr[k0 + 8] * sc, wr[k0 + 9] * sc);
                    wf[((m * 2 + j) * 4 + kt) * 2 + 0] = *(unsigned*)&lo;
                    wf[((m * 2 + j) * 4 + kt) * 2 + 1] = *(unsigned*)&hi;
                }
            }
        }
    }
    __syncthreads();

    const unsigned hbase   = smem_u32(hbuf[0]);
    const unsigned hbytes  = HSTRIDE * 2;                       // bytes per h buffer
    const unsigned laneoff = 2u * ((lane & 15) * LDH + (lane >> 4) * 8);

    if (wid < 16) {
        // =========== L0 producer group (512 threads) — R5 protocol ===========
        // Inner loop: both mt row-halves interleaved (amA/amB double-buffer the
        // ldsm streams; 4 serial waits instead of 8).
        const int w = wid;
        const float2 bif = bias0p[w * 8 + (lane & 3)];
        const float2 bgo = bias0p[w * 8 + 4 + (lane & 3)];
        const float2 wif = wih0p[w * 8 + (lane & 3)];
        const float2 wgo = wih0p[w * 8 + 4 + (lane & 3)];
        const int u0 = w * 4 + (lane & 3);
        int s = 0, sp = 2;
        for (int k = 0; k < SEQT; ++k) {
            if ((k & (XCH - 1)) == 0) {
                if (k) BSYNC(BAR_L0G, NL0);          // peers done with old chunk
                for (int i = tid; i < BROWS * XCH; i += NL0) {
                    int row = i >> 7, kl = i & (XCH - 1);
                    xs[kl * XLD + row] = x[(r0 + row) * SEQT + k + kl];
                }
                BSYNC(BAR_L0G, NL0);
            }
            if (k >= 3)      BSYNC(BAR_FREE + s, NTHREADS);  // L1 consumed slot s; groups L0
            else if (k >= 1) BSYNC(BAR_L0G, NL0);            // order peers' h1[k-1] writes

            const int kk = (k & (XCH - 1)) * XLD;
            float xv[4];
            #pragma unroll
            for (int i = 0; i < 4; i++) {
                int r = (lane >> 2) + 8 * (i & 1) + 16 * (i >> 1);
                xv[i] = xs[kk + r];
            }
            const unsigned h1rd = hbase + sp * hbytes + laneoff;

            float cf[16];
            cf[0] = bif.x; cf[1] = bif.y; cf[2]  = bif.x; cf[3]  = bif.y;
            cf[4] = bgo.x; cf[5] = bgo.y; cf[6]  = bgo.x; cf[7]  = bgo.y;
            cf[8] = bif.x; cf[9] = bif.y; cf[10] = bif.x; cf[11] = bif.y;
            cf[12] = bgo.x; cf[13] = bgo.y; cf[14] = bgo.x; cf[15] = bgo.y;
            #pragma unroll
            for (int kt = 0; kt < 4; kt++) {
                unsigned amA[4], amB[4];
                ldsm4(amA, h1rd + kt * 32);          // rows 0-15
                ldsm4(amB, h1rd + RB + kt * 32);     // rows 16-31
                mma16816(&cf[0],  amA, &wf[kt * 2]);
                mma16816(&cf[4],  amA, &wf[(4 + kt) * 2]);
                mma16816(&cf[8],  amB, &wf[kt * 2]);
                mma16816(&cf[12], amB, &wf[(4 + kt) * 2]);
            }
            #pragma unroll
            for (int mt = 0; mt < 2; mt++) {
                #pragma unroll
                for (int rh = 0; rh < 2; rh++) {
                    float xr = xv[mt * 2 + rh];
                    float ip = fmaf(xr, wif.x, cf[mt*8 + rh * 2 + 0]);
                    float fp = fmaf(xr, wif.y, cf[mt*8 + rh * 2 + 1]);
                    float gp = fmaf(xr, wgo.x, cf[mt*8 + 4 + rh * 2 + 0]);
                    float op = fmaf(xr, wgo.y, cf[mt*8 + 4 + rh * 2 + 1]);
                    int ci = mt * 2 + rh;
                    float2 ch = celltanh_ps(ip, fp, gp, op, cs[ci]);
                    cs[ci] = ch.x;
                    int r = 16 * mt + (lane >> 2) + 8 * rh;
                    hbuf[s][r * LDH + u0] = __float2half_rn(ch.y);
                }
            }
            MEMBAR_CTA();                       // publish h1[s] stores
            BARRIVE(BAR_FULL + s, NTHREADS);
            sp = s; s = (s == 2) ? 0 : s + 1;
        }
    } else {
        // =========== L1 consumer group (512 threads) — R5 protocol ===========
        // Inner loop: h1 and h2 ldsm streams interleaved per kt (amA/amB),
        // halving serial smem waits (16 -> 8 per step).
        const int w1 = wid - 16;
        const int u1 = w1 * 4 + (lane & 3);
        int s = 0;
        for (int k = 0; k < SEQT; ++k) {
            BSYNC(BAR_FULL + s, NTHREADS);      // h1[k] ready; also groups L1 (fences h2)
            const unsigned h1rd = hbase + s * hbytes + laneoff;
            const unsigned h2rd = hbase + (3 + ((k + 1) & 1)) * hbytes + laneoff;
            #pragma unroll
            for (int mt = 0; mt < 2; mt++) {
                float2 bif = bias1p[w1 * 8 + (lane & 3)];
                float2 bgo = bias1p[w1 * 8 + 4 + (lane & 3)];
                float cf[8];
                cf[0] = bif.x; cf[1] = bif.y; cf[2] = bif.x; cf[3] = bif.y;
                cf[4] = bgo.x; cf[5] = bgo.y; cf[6] = bgo.x; cf[7] = bgo.y;
                #pragma unroll
                for (int kt = 0; kt < 4; kt++) {
                    unsigned amA[4], amB[4];
                    ldsm4(amA, h1rd + mt * RB + kt * 32);   // h1_k
                    ldsm4(amB, h2rd + mt * RB + kt * 32);   // h2_{k-1}
                    mma16816(&cf[0], amA, &wf[kt * 2]);
                    mma16816(&cf[4], amA, &wf[(4 + kt) * 2]);
                    mma16816(&cf[0], amB, &wf[(8 + kt) * 2]);
                    mma16816(&cf[4], amB, &wf[(12 + kt) * 2]);
                }
                #pragma unroll
                for (int rh = 0; rh < 2; rh++) {
                    float ip = cf[rh * 2 + 0];
                    float fp = cf[rh * 2 + 1];
                    float gp = cf[4 + rh * 2 + 0];
                    float op = cf[4 + rh * 2 + 1];
                    int ci = mt * 2 + rh;
                    float2 ch = celltanh_ps(ip, fp, gp, op, cs[ci]);
                    cs[ci] = ch.x;
                    int r = 16 * mt + (lane >> 2) + 8 * rh;
                    hbuf[3 + (k & 1)][r * LDH + u1] = __float2half_rn(ch.y);
                }
            }
            BARRIVE(BAR_FREE + s, NTHREADS);    // h1[s] consumed
            s = (s == 2) ? 0 : s + 1;
        }
    }
    __syncthreads();

    // ---------------- linear head on h2_{T-1} ----------------
    if (tid < BROWS) {
        const __half* h2f = hbuf[3 + ((SEQT - 1) & 1)];
        float acc = b_lin[0];
        #pragma unroll
        for (int u = 0; u < HID; u++)
            acc += __half2float(h2f[tid * LDH + u]) * wlin_s[u];
        out[r0 + tid] = acc;
    }
}

extern "C" void kernel_launch(void* const* d_in, const int* in_sizes, int n_in,
                              void* d_out, int out_size) {
    const float* x     = (const float*)d_in[0];
    const float* w_ih0 = (const float*)d_in[1];
    const float* w_hh0 = (const float*)d_in[2];
    const float* b_ih0 = (const float*)d_in[3];
    const float* b_hh0 = (const float*)d_in[4];
    const float* w_ih1 = (const float*)d_in[5];
    const float* w_hh1 = (const float*)d_in[6];
    const float* b_ih1 = (const float*)d_in[7];
    const float* b_hh1 = (const float*)d_in[8];
    const float* w_lin = (const float*)d_in[9];
    const float* b_lin = (const float*)d_in[10];

    const int B = in_sizes[0] / SEQT;   // 4096
    const int grid = B / BROWS;         // 128

    lstm2_kernel<<<grid, NTHREADS>>>(x, w_ih0, w_hh0, b_ih0, b_hh0,
                                     w_ih1, w_hh1, b_ih1, b_hh1,
                                     w_lin, b_lin, (float*)d_out);
}

// round 14
// speedup vs baseline: 1.2379x; 1.1180x over previous
#include <cuda_runtime.h>
#include <cuda_fp16.h>

#define HID 64
#define SEQT 512
#define BROWS 32
#define LDH 72            // padded halves per h row (conflict-free ldmatrix)
#define NTHREADS 1024     // 32 warps: 16 x layer0, 16 x layer1
#define NL0 512           // threads in L0 group
#define XCH 128           // x chunk length staged in smem
#define XLD 33            // padded float stride for xs rows
#define HSTRIDE (BROWS * LDH)   // halves per h buffer

// named barriers: 1..3 = free[slot], 4..6 = full[slot], 7 = L0 group
#define BAR_FREE 1
#define BAR_FULL 4
#define BAR_L0G  7

#define BSYNC(id, cnt)   asm volatile("bar.sync %0, %1;"   :: "r"(id), "r"(cnt) : "memory")
#define BARRIVE(id, cnt) asm volatile("bar.arrive %0, %1;" :: "r"(id), "r"(cnt) : "memory")

__device__ __forceinline__ unsigned smem_u32(const void* p) {
    return (unsigned)__cvta_generic_to_shared(p);
}

__device__ __forceinline__ void ldsm4(unsigned a[4], unsigned addr) {
    asm volatile("ldmatrix.sync.aligned.m8n8.x4.shared.b16 {%0,%1,%2,%3}, [%4];\n"
        : "=r"(a[0]), "=r"(a[1]), "=r"(a[2]), "=r"(a[3]) : "r"(addr));
}

__device__ __forceinline__ void mma16816(float c[4], const unsigned a[4], const unsigned b[2]) {
    asm volatile("mma.sync.aligned.m16n8k16.row.col.f32.f16.f16.f32 "
        "{%0,%1,%2,%3},{%4,%5,%6,%7},{%8,%9},{%0,%1,%2,%3};\n"
        : "+f"(c[0]), "+f"(c[1]), "+f"(c[2]), "+f"(c[3])
        : "r"(a[0]), "r"(a[1]), "r"(a[2]), "r"(a[3]), "r"(b[0]), "r"(b[1]));
}

__device__ __forceinline__ float tanh_hw(float x) {
    float y;
    asm("tanh.approx.f32 %0, %1;" : "=f"(y) : "f"(x));
    return y;
}

// LSTM cell, i/f/o pre-activations PRE-SCALED by 0.5 (folded into weights/bias).
// sigmoid(2x') = 0.5*tanh(x')+0.5. 5 MUFU + 6 fma-pipe ops.
__device__ __forceinline__ float2 celltanh_ps(float ip, float fp, float gp, float op, float c) {
    float ti = tanh_hw(ip);
    float tf = tanh_hw(fp);
    float to = tanh_hw(op);
    float tg = tanh_hw(gp);
    float si = fmaf(ti, 0.5f, 0.5f);
    float sf = fmaf(tf, 0.5f, 0.5f);
    float so = fmaf(to, 0.5f, 0.5f);
    float cn = fmaf(sf, c, si * tg);
    float tc = tanh_hw(cn);
    return make_float2(cn, so * tc);
}

__global__ void __launch_bounds__(NTHREADS, 1)
lstm2_kernel(const float* __restrict__ x,
             const float* __restrict__ w_ih0, const float* __restrict__ w_hh0,
             const float* __restrict__ b_ih0, const float* __restrict__ b_hh0,
             const float* __restrict__ w_ih1, const float* __restrict__ w_hh1,
             const float* __restrict__ b_ih1, const float* __restrict__ b_hh1,
             const float* __restrict__ w_lin, const float* __restrict__ b_lin,
             float* __restrict__ out)
{
    __shared__ __half hbuf[5][HSTRIDE];  // [0..2]=h1 ring, [3,4]=h2 double buffer
    __shared__ float2 bias0p[128];   // layer0 combined bias, permuted (i/f/o x0.5)
    __shared__ float2 wih0p[128];    // layer0 input weights, permuted (i/f/o x0.5)
    __shared__ float2 bias1p[128];   // layer1 combined bias, permuted (i/f/o x0.5)
    __shared__ float  wlin_s[HID];
    __shared__ float  xs[XCH * XLD]; // staged x chunk, transposed [k][row]

    const int tid  = threadIdx.x;
    const int wid  = tid >> 5;
    const int lane = tid & 31;
    const int r0   = blockIdx.x * BROWS;

    // ---------------- init: permuted bias / w_ih0 tables ----------------
    // Both layers: 16 warps x 16 gate-cols. idx = w*16 + j*8 + c,
    // unit u = w*4 + (c>>1), gate g = j*2 + (c&1). Gate 2 (=g) unscaled; i/f/o x0.5.
    if (tid < 256) {
        int w = tid >> 4, rem = tid & 15, j = rem >> 3, c = rem & 7;
        int u = w * 4 + (c >> 1);
        int g = j * 2 + (c & 1);
        int row = g * HID + u;
        float sc = (g == 2) ? 1.0f : 0.5f;
        ((float*)bias0p)[tid] = (b_ih0[row] + b_hh0[row]) * sc;
        ((float*)wih0p)[tid]  = w_ih0[row] * sc;
        ((float*)bias1p)[tid] = (b_ih1[row] + b_hh1[row]) * sc;
    }
    if (tid < HID) wlin_s[tid] = w_lin[tid];
    for (int i = tid; i < HSTRIDE; i += NTHREADS) {
        hbuf[2][i] = __float2half(0.0f);   // h1[-1]
        hbuf[3][i] = __float2half(0.0f);
        hbuf[4][i] = __float2half(0.0f);   // h2[-1]
    }

    // ---------------- preload weight B-fragments into registers ----------------
    unsigned wf[32];          // L0 uses [0..15], L1 uses all 32
    float    cs[4];
    #pragma unroll
    for (int i = 0; i < 4; i++) cs[i] = 0.0f;

    const int cB = lane >> 2;
    const int kq = lane & 3;

    if (wid < 16) {
        const int w = wid;
        #pragma unroll
        for (int j = 0; j < 2; j++) {
            int u = w * 4 + (cB >> 1);
            int g = j * 2 + (cB & 1);
            float sc = (g == 2) ? 1.0f : 0.5f;
            const float* wr = w_hh0 + (g * HID + u) * HID;
            #pragma unroll
            for (int kt = 0; kt < 4; kt++) {
                int k0 = kt * 16 + 2 * kq;
                __half2 lo = __floats2half2_rn(wr[k0] * sc,     wr[k0 + 1] * sc);
                __half2 hi = __floats2half2_rn(wr[k0 + 8] * sc, wr[k0 + 9] * sc);
                wf[(j * 4 + kt) * 2 + 0] = *(unsigned*)&lo;
                wf[(j * 4 + kt) * 2 + 1] = *(unsigned*)&hi;
            }
        }
    } else {
        const int w1 = wid - 16;
        #pragma unroll
        for (int m = 0; m < 2; m++) {
            const float* W = m ? w_hh1 : w_ih1;
            #pragma unroll
            for (int j = 0; j < 2; j++) {
                int u = w1 * 4 + (cB >> 1);
                int g = j * 2 + (cB & 1);
                float sc = (g == 2) ? 1.0f : 0.5f;
                const float* wr = W + (g * HID + u) * HID;
                #pragma unroll
                for (int kt = 0; kt < 4; kt++) {
                    int k0 = kt * 16 + 2 * kq;
                    __half2 lo = __floats2half2_rn(wr[k0] * sc,     wr[k0 + 1] * sc);
                    __half2 hi = __floats2half2_rn(wr[k0 + 8] * sc, wr[k0 + 9] * sc);
                    wf[((m * 2 + j) * 4 + kt) * 2 + 0] = *(unsigned*)&lo;
                    wf[((m * 2 + j) * 4 + kt) * 2 + 1] = *(unsigned*)&hi;
                }
            }
        }
    }
    __syncthreads();

    const unsigned hbase   = smem_u32(hbuf[0]);
    const unsigned hbytes  = HSTRIDE * 2;                       // bytes per h buffer
    const unsigned laneoff = 2u * ((lane & 15) * LDH + (lane >> 4) * 8);

    if (wid < 16) {
        // =========== L0 producer group (512 threads) — R5 protocol ===========
        const int w = wid;
        const float2 bif = bias0p[w * 8 + (lane & 3)];
        const float2 bgo = bias0p[w * 8 + 4 + (lane & 3)];
        const float2 wif = wih0p[w * 8 + (lane & 3)];
        const float2 wgo = wih0p[w * 8 + 4 + (lane & 3)];
        const int u0 = w * 4 + (lane & 3);
        int s = 0, sp = 2;
        for (int k = 0; k < SEQT; ++k) {
            if ((k & (XCH - 1)) == 0) {
                if (k) BSYNC(BAR_L0G, NL0);          // peers done with old chunk
                for (int i = tid; i < BROWS * XCH; i += NL0) {
                    int row = i >> 7;          // i / XCH
                    int kl  = i & (XCH - 1);
                    xs[kl * XLD + row] = x[(r0 + row) * SEQT + k + kl];
                }
                BSYNC(BAR_L0G, NL0);
            }
            // xv depends only on xs (stable within chunk) — load BEFORE the
            // slot wait so the LDS latency overlaps the barrier.
            const int kk = (k & (XCH - 1)) * XLD;
            float xv[4];
            #pragma unroll
            for (int i = 0; i < 4; i++) {
                int r = (lane >> 2) + 8 * (i & 1) + 16 * (i >> 1);
                xv[i] = xs[kk + r];
            }

            if (k >= 3)      BSYNC(BAR_FREE + s, NTHREADS);  // L1 consumed slot s; groups L0
            else if (k >= 1) BSYNC(BAR_L0G, NL0);            // order peers' h1[k-1] writes

            const unsigned h1rd = hbase + sp * hbytes + laneoff;
            #pragma unroll
            for (int mt = 0; mt < 2; mt++) {
                float cf[8];
                cf[0] = bif.x; cf[1] = bif.y; cf[2] = bif.x; cf[3] = bif.y;
                cf[4] = bgo.x; cf[5] = bgo.y; cf[6] = bgo.x; cf[7] = bgo.y;
                #pragma unroll
                for (int kt = 0; kt < 4; kt++) {
                    unsigned am[4];
                    ldsm4(am, h1rd + mt * (16 * LDH * 2) + kt * 32);
                    mma16816(&cf[0], am, &wf[kt * 2]);
                    mma16816(&cf[4], am, &wf[(4 + kt) * 2]);
                }
                #pragma unroll
                for (int rh = 0; rh < 2; rh++) {
                    float xr = xv[mt * 2 + rh];
                    float ip = fmaf(xr, wif.x, cf[rh * 2 + 0]);
                    float fp = fmaf(xr, wif.y, cf[rh * 2 + 1]);
                    float gp = fmaf(xr, wgo.x, cf[4 + rh * 2 + 0]);
                    float op = fmaf(xr, wgo.y, cf[4 + rh * 2 + 1]);
                    int ci = mt * 2 + rh;
                    float2 ch = celltanh_ps(ip, fp, gp, op, cs[ci]);
                    cs[ci] = ch.x;
                    int r = 16 * mt + (lane >> 2) + 8 * rh;
                    hbuf[s][r * LDH + u0] = __float2half_rn(ch.y);
                }
            }
            // No explicit membar: bar.arrive(release) -> consumer bar.sync(acquire)
            // plus the in-order per-SM L1TEX queue orders STS before consumer LDSM.
            BARRIVE(BAR_FULL + s, NTHREADS);
            sp = s; s = (s == 2) ? 0 : s + 1;
        }
    } else {
        // =========== L1 consumer group (512 threads) — R5 protocol ===========
        const int w1 = wid - 16;
        const float2 bif = bias1p[w1 * 8 + (lane & 3)];
        const float2 bgo = bias1p[w1 * 8 + 4 + (lane & 3)];
        const int u1 = w1 * 4 + (lane & 3);
        int s = 0;
        for (int k = 0; k < SEQT; ++k) {
            BSYNC(BAR_FULL + s, NTHREADS);      // h1[k] ready; also groups L1 (fences h2)
            const unsigned h1rd = hbase + s * hbytes + laneoff;
            const unsigned h2rd = hbase + (3 + ((k + 1) & 1)) * hbytes + laneoff;
            #pragma unroll
            for (int mt = 0; mt < 2; mt++) {
                float cf[8];
                cf[0] = bif.x; cf[1] = bif.y; cf[2] = bif.x; cf[3] = bif.y;
                cf[4] = bgo.x; cf[5] = bgo.y; cf[6] = bgo.x; cf[7] = bgo.y;
                #pragma unroll
                for (int kt = 0; kt < 4; kt++) {       // h1_k @ w_ih1^T
                    unsigned am[4];
                    ldsm4(am, h1rd + mt * (16 * LDH * 2) + kt * 32);
                    mma16816(&cf[0], am, &wf[kt * 2]);
                    mma16816(&cf[4], am, &wf[(4 + kt) * 2]);
                }
                #pragma unroll
                for (int kt = 0; kt < 4; kt++) {       // h2_{k-1} @ w_hh1^T
                    unsigned am[4];
                    ldsm4(am, h2rd + mt * (16 * LDH * 2) + kt * 32);
                    mma16816(&cf[0], am, &wf[(8 + kt) * 2]);
                    mma16816(&cf[4], am, &wf[(12 + kt) * 2]);
                }
                #pragma unroll
                for (int rh = 0; rh < 2; rh++) {
                    float ip = cf[rh * 2 + 0];
                    float fp = cf[rh * 2 + 1];
                    float gp = cf[4 + rh * 2 + 0];
                    float op = cf[4 + rh * 2 + 1];
                    int ci = mt * 2 + rh;
                    float2 ch = celltanh_ps(ip, fp, gp, op, cs[ci]);
                    cs[ci] = ch.x;
                    int r = 16 * mt + (lane >> 2) + 8 * rh;
                    hbuf[3 + (k & 1)][r * LDH + u1] = __float2half_rn(ch.y);
                }
            }
            BARRIVE(BAR_FREE + s, NTHREADS);    // h1[s] consumed
            s = (s == 2) ? 0 : s + 1;
        }
    }
    __syncthreads();

    // ---------------- linear head on h2_{T-1} ----------------
    if (tid < BROWS) {
        const __half* h2f = hbuf[3 + ((SEQT - 1) & 1)];
        float acc = b_lin[0];
        #pragma unroll
        for (int u = 0; u < HID; u++)
            acc += __half2float(h2f[tid * LDH + u]) * wlin_s[u];
        out[r0 + tid] = acc;
    }
}

extern "C" void kernel_launch(void* const* d_in, const int* in_sizes, int n_in,
                              void* d_out, int out_size) {
    const float* x     = (const float*)d_in[0];
    const float* w_ih0 = (const float*)d_in[1];
    const float* w_hh0 = (const float*)d_in[2];
    const float* b_ih0 = (const float*)d_in[3];
    const float* b_hh0 = (const float*)d_in[4];
    const float* w_ih1 = (const float*)d_in[5];
    const float* w_hh1 = (const float*)d_in[6];
    const float* b_ih1 = (const float*)d_in[7];
    const float* b_hh1 = (const float*)d_in[8];
    const float* w_lin = (const float*)d_in[9];
    const float* b_lin = (const float*)d_in[10];

    const int B = in_sizes[0] / SEQT;   // 4096
    const int grid = B / BROWS;         // 128

    lstm2_kernel<<<grid, NTHREADS>>>(x, w_ih0, w_hh0, b_ih0, b_hh0,
                                     w_ih1, w_hh1, b_ih1, b_hh1,
                                     w_lin, b_lin, (float*)d_out);
}